// round 11
// baseline (speedup 1.0000x reference)
#include <cuda_runtime.h>
#include <cuda_fp16.h>
#include <cstdint>

// ---------------- problem constants ----------------
#define TOKENS 512
#define OUT_F  8192
#define IN_F   4096

#define BM 128
#define BN 128
#define BK 64
#define NKT (IN_F / BK)   // 64 k-tiles
#define NTHREADS 256

// ---------------- persistent scratch (device global; no runtime alloc) ----
__device__ static __half g_x16[TOKENS * IN_F];          // 4 MB

// ---------------- smem layout (dynamic) ----------------
#define OFF_ALPHA   0
#define OFF_BIAS    512
#define OFF_TILE    1024
// per buffer: A 128x64 fp16 (16KB) | B 128x64 fp16 (16KB)
#define TILE_STRIDE 32768
#define SMEM_BYTES  (OFF_TILE + 2 * TILE_STRIDE)   // 66560

// SW128-style XOR swizzle on 128B rows
#define SWZ(o) ((uint32_t)(o) ^ ((((uint32_t)(o)) >> 3) & 0x70))

__device__ __forceinline__ uint32_t smem_u32(const void* p) {
    uint32_t a;
    asm("{ .reg .u64 t; cvta.to.shared.u64 t, %1; cvt.u32.u64 %0, t; }"
        : "=r"(a) : "l"(p));
    return a;
}

#define LDSM4(R, addr) \
    asm volatile("ldmatrix.sync.aligned.m8n8.x4.shared.b16 {%0,%1,%2,%3}, [%4];" \
        : "=r"((R)[0]), "=r"((R)[1]), "=r"((R)[2]), "=r"((R)[3]) : "r"(addr))

#define MMA16816(C, A, b0, b1) \
    asm volatile("mma.sync.aligned.m16n8k16.row.col.f32.f16.f16.f32 " \
        "{%0,%1,%2,%3},{%4,%5,%6,%7},{%8,%9},{%0,%1,%2,%3};" \
        : "+f"((C)[0]), "+f"((C)[1]), "+f"((C)[2]), "+f"((C)[3]) \
        : "r"((A)[0]), "r"((A)[1]), "r"((A)[2]), "r"((A)[3]), "r"(b0), "r"(b1))

#define CP16(dst, src) \
    asm volatile("cp.async.cg.shared.global [%0], [%1], 16;" \
        :: "r"(dst), "l"(__cvta_generic_to_global(src)) : "memory")
#define CP_COMMIT() asm volatile("cp.async.commit_group;" ::: "memory")
#define CP_WAIT0()  asm volatile("cp.async.wait_group 0;" ::: "memory")

__device__ __forceinline__ uint32_t f16x2(float a, float b) {
    __half2 h = __floats2half2_rn(a, b);
    return *reinterpret_cast<uint32_t*>(&h);
}

// code -> fp16 bits: 0 -> 0xBC00 (-1), 1 -> 0, 2 -> 0x3C00 (+1), 3 -> 0
// (only the low byte of each packed int32 carries codes)
__device__ __forceinline__ uint2 dec_word(int word) {
    const uint64_t T = 0x00003C000000BC00ull;
    uint32_t h0 = (uint32_t)(T >> ((word & 3) << 4)) & 0xFFFFu;
    uint32_t h1 = (uint32_t)(T >> (((word >> 2) & 3) << 4)) & 0xFFFFu;
    uint32_t h2 = (uint32_t)(T >> (((word >> 4) & 3) << 4)) & 0xFFFFu;
    uint32_t h3 = (uint32_t)(T >> (((word >> 6) & 3) << 4)) & 0xFFFFu;
    return make_uint2(h0 | (h1 << 16), h2 | (h3 << 16));
}

// ---------------- pre-kernel: x fp32 -> fp16 ----------------
__global__ void conv_x_fp16(const float4* __restrict__ x4) {
    uint32_t u = blockIdx.x * 256 + threadIdx.x;   // 524288 threads
    float4 v = x4[u];
    uint2 h;
    h.x = f16x2(v.x, v.y);
    h.y = f16x2(v.z, v.w);
    reinterpret_cast<uint2*>(g_x16)[u] = h;
}

// ---------------- main GEMM ----------------
__global__ void __launch_bounds__(NTHREADS, 2)
ternary_gemm_fp16(const int*   __restrict__ wp,
                  const float* __restrict__ alpha,
                  const float* __restrict__ bias,
                  float*       __restrict__ out) {
    extern __shared__ char smem[];
    const uint32_t sb = smem_u32(smem);
    const int tid = threadIdx.x;
    const int wid = tid >> 5;
    const int L   = tid & 31;

    const int n0 = blockIdx.x * BN;   // output-feature tile
    const int m0 = blockIdx.y * BM;   // token tile

    const int wm = (wid & 1) * 64;    // warp m offset
    const int wn = (wid >> 1) * 32;   // warp n offset

    // ---------------- prologue: alpha/bias ----------------
    if (tid < BN) {
        reinterpret_cast<float*>(smem + OFF_ALPHA)[tid] = alpha[n0 + tid];
        reinterpret_cast<float*>(smem + OFF_BIAS)[tid]  = bias[n0 + tid];
    }

    // ---------------- per-lane ldmatrix address constants ----------------
    // A: [m][k] rows of 128B. x4: (m0-7,k0-7),(m8-15,k0-7),(m0-7,k8-15),(m8-15,k8-15)
    const int mrow = ((L >> 3) & 1) * 8 + (L & 7);
    const uint32_t a_kx  = (uint32_t)(L >> 4) * 16;
    const uint32_t axor  = (uint32_t)(mrow & 7) << 4;
    const uint32_t a_row = (uint32_t)(wm + mrow) * 128;
    // B: [n][k] rows of 128B. x4: (n0-7,k0-7),(n0-7,k8-15),(n8-15,k0-7),(n8-15,k8-15)
    const int nrow = (L >> 4) * 8 + (L & 7);
    const uint32_t b_kx  = (uint32_t)((L >> 3) & 1) * 16;
    const uint32_t bxor  = (uint32_t)(nrow & 7) << 4;
    const uint32_t b_row = (uint32_t)(wn + nrow) * 128;

    const __half* gx = g_x16;
    const int4*   w4g = reinterpret_cast<const int4*>(wp);

    // A cp.async staging: 1024 chunks of 16B; 4 chunks/thread
    const int cm = tid >> 3;          // rows cm + 32*i
    const int cj = tid & 7;           // 16B chunk within 128B row
    // B staging: 512 int4 units (int4 = 4 words = 16 k); 2 per thread
    const int bn0 = (tid + 0 * NTHREADS) >> 2, bq0 = (tid + 0 * NTHREADS) & 3;
    const int bn1 = (tid + 1 * NTHREADS) >> 2, bq1 = (tid + 1 * NTHREADS) & 3;

    float acc[4][4][4];
    #pragma unroll
    for (int i = 0; i < 4; i++)
        #pragma unroll
        for (int j = 0; j < 4; j++)
            #pragma unroll
            for (int q = 0; q < 4; q++) acc[ i][j][q] = 0.0f;

    int4 wv[2];

    // ---- prologue tile 0: A via cp.async, B decode to smem ----
    {
        const uint32_t ab = sb + OFF_TILE;
        const uint32_t bb = ab + 16384;
        #pragma unroll
        for (int i = 0; i < 4; i++) {
            int m = cm + i * 32;
            uint32_t dst = ab + SWZ((uint32_t)m * 128 + (uint32_t)cj * 16);
            CP16(dst, gx + (size_t)(m0 + m) * IN_F + cj * 8);
        }
        CP_COMMIT();
        wv[0] = w4g[(uint32_t)(n0 + bn0) * (IN_F / 16) + bq0];
        wv[1] = w4g[(uint32_t)(n0 + bn1) * (IN_F / 16) + bq1];
        #pragma unroll
        for (int i = 0; i < 2; i++) {
            const int bn_ = i ? bn1 : bn0;
            const int bq_ = i ? bq1 : bq0;
            uint2 d0 = dec_word(wv[i].x), d1 = dec_word(wv[i].y);
            uint2 d2 = dec_word(wv[i].z), d3 = dec_word(wv[i].w);
            uint32_t o0 = (uint32_t)bn_ * 128 + (uint32_t)bq_ * 32;
            asm volatile("st.shared.v4.b32 [%0], {%1,%2,%3,%4};"
                :: "r"(bb + SWZ(o0)), "r"(d0.x), "r"(d0.y), "r"(d1.x), "r"(d1.y));
            asm volatile("st.shared.v4.b32 [%0], {%1,%2,%3,%4};"
                :: "r"(bb + SWZ(o0 + 16)), "r"(d2.x), "r"(d2.y), "r"(d3.x), "r"(d3.y));
        }
    }

    // ---------------- main K loop ----------------
    #pragma unroll 1
    for (int kt = 0; kt < NKT; kt++) {
        CP_WAIT0();
        __syncthreads();   // tile kt fully resident (A cp.async + B STS)

        // issue next A tile via cp.async; load next packed B into regs
        if (kt + 1 < NKT) {
            const uint32_t ab = sb + OFF_TILE + (uint32_t)((kt + 1) & 1) * TILE_STRIDE;
            const int kk = (kt + 1) * BK + cj * 8;
            #pragma unroll
            for (int i = 0; i < 4; i++) {
                int m = cm + i * 32;
                uint32_t dst = ab + SWZ((uint32_t)m * 128 + (uint32_t)cj * 16);
                CP16(dst, gx + (size_t)(m0 + m) * IN_F + kk);
            }
            wv[0] = w4g[(uint32_t)(n0 + bn0) * (IN_F / 16) + (kt + 1) * 4 + bq0];
            wv[1] = w4g[(uint32_t)(n0 + bn1) * (IN_F / 16) + (kt + 1) * 4 + bq1];
        }
        CP_COMMIT();

        // ---- MMA on current buffer ----
        {
            const uint32_t base = sb + OFF_TILE + (uint32_t)(kt & 1) * TILE_STRIDE;
            const uint32_t ahb = base + a_row;
            const uint32_t bbb = base + 16384 + b_row;
            #pragma unroll
            for (int ks = 0; ks < 4; ks++) {
                const uint32_t koffa = ((uint32_t)(ks * 32) + a_kx) ^ axor;
                const uint32_t koffb = ((uint32_t)(ks * 32) + b_kx) ^ bxor;
                uint32_t bf[8];
                LDSM4(bf,     bbb + koffb);          // n atoms 0,1
                LDSM4(bf + 4, bbb + 2048 + koffb);   // n atoms 2,3
                #pragma unroll
                for (int ma = 0; ma < 4; ma++) {
                    uint32_t af[4];
                    LDSM4(af, ahb + (uint32_t)ma * 2048 + koffa);
                    MMA16816(acc[ma][0], af, bf[0], bf[1]);
                    MMA16816(acc[ma][1], af, bf[2], bf[3]);
                    MMA16816(acc[ma][2], af, bf[4], bf[5]);
                    MMA16816(acc[ma][3], af, bf[6], bf[7]);
                }
            }
        }

        // ---- decode next B tile into other buffer ----
        if (kt + 1 < NKT) {
            const uint32_t bb = sb + OFF_TILE + (uint32_t)((kt + 1) & 1) * TILE_STRIDE + 16384;
            #pragma unroll
            for (int i = 0; i < 2; i++) {
                const int bn_ = i ? bn1 : bn0;
                const int bq_ = i ? bq1 : bq0;
                uint2 d0 = dec_word(wv[i].x), d1 = dec_word(wv[i].y);
                uint2 d2 = dec_word(wv[i].z), d3 = dec_word(wv[i].w);
                uint32_t o0 = (uint32_t)bn_ * 128 + (uint32_t)bq_ * 32;
                asm volatile("st.shared.v4.b32 [%0], {%1,%2,%3,%4};"
                    :: "r"(bb + SWZ(o0)), "r"(d0.x), "r"(d0.y), "r"(d1.x), "r"(d1.y));
                asm volatile("st.shared.v4.b32 [%0], {%1,%2,%3,%4};"
                    :: "r"(bb + SWZ(o0 + 16)), "r"(d2.x), "r"(d2.y), "r"(d3.x), "r"(d3.y));
            }
        }
    }

    // ---------------- epilogue ----------------
    const float* alpS = reinterpret_cast<const float*>(smem + OFF_ALPHA);
    const float* biaS = reinterpret_cast<const float*>(smem + OFF_BIAS);
    const int r  = L >> 2;
    const int c2 = (L & 3) * 2;

    #pragma unroll
    for (int ma = 0; ma < 4; ma++) {
        #pragma unroll
        for (int na = 0; na < 4; na++) {
            int cl = wn + na * 8 + c2;
            float A0 = alpS[cl], A1 = alpS[cl + 1];
            float B0 = biaS[cl], B1 = biaS[cl + 1];
            int gm = m0 + wm + ma * 16 + r;
            float* p = out + (uint32_t)gm * OUT_F + n0 + cl;
            float2 v0 = make_float2(fmaf(acc[ma][na][0], A0, B0),
                                    fmaf(acc[ma][na][1], A1, B1));
            *reinterpret_cast<float2*>(p) = v0;
            float2 v1 = make_float2(fmaf(acc[ma][na][2], A0, B0),
                                    fmaf(acc[ma][na][3], A1, B1));
            *reinterpret_cast<float2*>(p + 8 * OUT_F) = v1;
        }
    }
}

extern "C" void kernel_launch(void* const* d_in, const int* in_sizes, int n_in,
                              void* d_out, int out_size) {
    const float* x     = (const float*)d_in[0];
    const int*   wp    = (const int*)d_in[1];
    const float* alpha = (const float*)d_in[2];
    const float* bias  = (const float*)d_in[3];
    float*       out   = (float*)d_out;

    static bool configured = false;
    if (!configured) {
        cudaFuncSetAttribute(ternary_gemm_fp16,
                             cudaFuncAttributeMaxDynamicSharedMemorySize, SMEM_BYTES);
        configured = true;
    }

    // pre-kernel: x fp32 -> fp16 (4 MB)
    conv_x_fp16<<<TOKENS * IN_F / 4 / 256, 256>>>(
        reinterpret_cast<const float4*>(x));

    dim3 grid(OUT_F / BN, TOKENS / BM);   // (64, 4) = 256 CTAs
    ternary_gemm_fp16<<<grid, NTHREADS, SMEM_BYTES>>>(wp, alpha, bias, out);
}

// round 12
// speedup vs baseline: 1.0396x; 1.0396x over previous
#include <cuda_runtime.h>
#include <cuda_fp16.h>
#include <cstdint>

// ---------------- problem constants ----------------
#define TOKENS 512
#define OUT_F  8192
#define IN_F   4096

#define BM 128
#define BN 128
#define BK 64
#define NKT (IN_F / BK)   // 64 k-tiles
#define NTHREADS 256

// ---------------- persistent scratch (device global; no runtime alloc) ----
__device__ static __half g_x16[TOKENS * IN_F];          // 4 MB

// ---------------- smem layout (dynamic) ----------------
#define OFF_ALPHA   0
#define OFF_BIAS    512
#define OFF_TILE    1024
// per buffer: A 128x64 fp16 (16KB) | B 128x64 fp16 (16KB)
#define TILE_STRIDE 32768
#define SMEM_BYTES  (OFF_TILE + 2 * TILE_STRIDE)   // 66560

// SW128-style XOR swizzle on 128B rows
#define SWZ(o) ((uint32_t)(o) ^ ((((uint32_t)(o)) >> 3) & 0x70))

__device__ __forceinline__ uint32_t smem_u32(const void* p) {
    uint32_t a;
    asm("{ .reg .u64 t; cvta.to.shared.u64 t, %1; cvt.u32.u64 %0, t; }"
        : "=r"(a) : "l"(p));
    return a;
}

#define LDSM4(R, addr) \
    asm volatile("ldmatrix.sync.aligned.m8n8.x4.shared.b16 {%0,%1,%2,%3}, [%4];" \
        : "=r"((R)[0]), "=r"((R)[1]), "=r"((R)[2]), "=r"((R)[3]) : "r"(addr))

#define MMA16816(C, A, b0, b1) \
    asm volatile("mma.sync.aligned.m16n8k16.row.col.f32.f16.f16.f32 " \
        "{%0,%1,%2,%3},{%4,%5,%6,%7},{%8,%9},{%0,%1,%2,%3};" \
        : "+f"((C)[0]), "+f"((C)[1]), "+f"((C)[2]), "+f"((C)[3]) \
        : "r"((A)[0]), "r"((A)[1]), "r"((A)[2]), "r"((A)[3]), "r"(b0), "r"(b1))

#define CP16(dst, src) \
    asm volatile("cp.async.cg.shared.global [%0], [%1], 16;" \
        :: "r"(dst), "l"(__cvta_generic_to_global(src)) : "memory")
#define CP_COMMIT() asm volatile("cp.async.commit_group;" ::: "memory")
#define CP_WAIT0()  asm volatile("cp.async.wait_group 0;" ::: "memory")

__device__ __forceinline__ uint32_t f16x2(float a, float b) {
    __half2 h = __floats2half2_rn(a, b);
    return *reinterpret_cast<uint32_t*>(&h);
}

// code -> fp16 bits: 0 -> 0xBC00 (-1), 1 -> 0, 2 -> 0x3C00 (+1), 3 -> 0
// (only the low byte of each packed int32 carries codes)
__device__ __forceinline__ uint2 dec_word(int word) {
    const uint64_t T = 0x00003C000000BC00ull;
    uint32_t h0 = (uint32_t)(T >> ((word & 3) << 4)) & 0xFFFFu;
    uint32_t h1 = (uint32_t)(T >> (((word >> 2) & 3) << 4)) & 0xFFFFu;
    uint32_t h2 = (uint32_t)(T >> (((word >> 4) & 3) << 4)) & 0xFFFFu;
    uint32_t h3 = (uint32_t)(T >> (((word >> 6) & 3) << 4)) & 0xFFFFu;
    return make_uint2(h0 | (h1 << 16), h2 | (h3 << 16));
}

// ---------------- pre-kernel: x fp32 -> fp16 ----------------
__global__ void conv_x_fp16(const float4* __restrict__ x4) {
    uint32_t u = blockIdx.x * 256 + threadIdx.x;   // 524288 threads
    float4 v = x4[u];
    uint2 h;
    h.x = f16x2(v.x, v.y);
    h.y = f16x2(v.z, v.w);
    reinterpret_cast<uint2*>(g_x16)[u] = h;
}

// ---------------- main GEMM ----------------
__global__ void __launch_bounds__(NTHREADS, 2)
ternary_gemm_fp16(const int*   __restrict__ wp,
                  const float* __restrict__ alpha,
                  const float* __restrict__ bias,
                  float*       __restrict__ out) {
    extern __shared__ char smem[];
    const uint32_t sb = smem_u32(smem);
    const int tid = threadIdx.x;
    const int wid = tid >> 5;
    const int L   = tid & 31;

    const int n0 = blockIdx.x * BN;   // output-feature tile
    const int m0 = blockIdx.y * BM;   // token tile

    const int wm = (wid & 1) * 64;    // warp m offset
    const int wn = (wid >> 1) * 32;   // warp n offset

    // ---------------- prologue: alpha/bias ----------------
    if (tid < BN) {
        reinterpret_cast<float*>(smem + OFF_ALPHA)[tid] = alpha[n0 + tid];
        reinterpret_cast<float*>(smem + OFF_BIAS)[tid]  = bias[n0 + tid];
    }

    // ---------------- per-lane ldmatrix address constants ----------------
    // A: [m][k] rows of 128B. x4: (m0-7,k0-7),(m8-15,k0-7),(m0-7,k8-15),(m8-15,k8-15)
    const int mrow = ((L >> 3) & 1) * 8 + (L & 7);
    const uint32_t a_kx  = (uint32_t)(L >> 4) * 16;
    const uint32_t axor  = (uint32_t)(mrow & 7) << 4;
    const uint32_t a_row = (uint32_t)(wm + mrow) * 128;
    // B: [n][k] rows of 128B. x4: (n0-7,k0-7),(n0-7,k8-15),(n8-15,k0-7),(n8-15,k8-15)
    const int nrow = (L >> 4) * 8 + (L & 7);
    const uint32_t b_kx  = (uint32_t)((L >> 3) & 1) * 16;
    const uint32_t bxor  = (uint32_t)(nrow & 7) << 4;
    const uint32_t b_row = (uint32_t)(wn + nrow) * 128;

    const __half* gx = g_x16;
    const int4*   w4g = reinterpret_cast<const int4*>(wp);

    // A cp.async staging: 1024 chunks of 16B; 4 chunks/thread
    const int cm = tid >> 3;          // rows cm + 32*i
    const int cj = tid & 7;           // 16B chunk within 128B row
    // B staging: 512 int4 units (int4 = 4 words = 16 k); 2 per thread
    const int bn0 = (tid + 0 * NTHREADS) >> 2, bq0 = (tid + 0 * NTHREADS) & 3;
    const int bn1 = (tid + 1 * NTHREADS) >> 2, bq1 = (tid + 1 * NTHREADS) & 3;
    const uint32_t bo0 = (uint32_t)bn0 * 128 + (uint32_t)bq0 * 32;
    const uint32_t bo1 = (uint32_t)bn1 * 128 + (uint32_t)bq1 * 32;

    float acc[4][4][4];
    #pragma unroll
    for (int i = 0; i < 4; i++)
        #pragma unroll
        for (int j = 0; j < 4; j++)
            #pragma unroll
            for (int q = 0; q < 4; q++) acc[i][j][q] = 0.0f;

    int4 wv[2];

    // ---- prologue tile 0: A via cp.async, B decode to smem ----
    {
        const uint32_t ab = sb + OFF_TILE;
        const uint32_t bb = ab + 16384;
        #pragma unroll
        for (int i = 0; i < 4; i++) {
            int m = cm + i * 32;
            uint32_t dst = ab + SWZ((uint32_t)m * 128 + (uint32_t)cj * 16);
            CP16(dst, gx + (size_t)(m0 + m) * IN_F + cj * 8);
        }
        CP_COMMIT();
        wv[0] = w4g[(uint32_t)(n0 + bn0) * (IN_F / 16) + bq0];
        wv[1] = w4g[(uint32_t)(n0 + bn1) * (IN_F / 16) + bq1];
        #pragma unroll
        for (int i = 0; i < 2; i++) {
            const uint32_t o0 = i ? bo1 : bo0;
            uint2 d0 = dec_word(wv[i].x), d1 = dec_word(wv[i].y);
            uint2 d2 = dec_word(wv[i].z), d3 = dec_word(wv[i].w);
            asm volatile("st.shared.v4.b32 [%0], {%1,%2,%3,%4};"
                :: "r"(bb + SWZ(o0)), "r"(d0.x), "r"(d0.y), "r"(d1.x), "r"(d1.y));
            asm volatile("st.shared.v4.b32 [%0], {%1,%2,%3,%4};"
                :: "r"(bb + SWZ(o0 + 16)), "r"(d2.x), "r"(d2.y), "r"(d3.x), "r"(d3.y));
        }
    }

    // ---------------- main K loop ----------------
    #pragma unroll 1
    for (int kt = 0; kt < NKT; kt++) {
        const bool more = (kt + 1 < NKT);

        // issue next packed-B LDG BEFORE the barrier — latency overlaps the
        // barrier wait + cp.async issue + early MMA steps
        if (more) {
            wv[0] = w4g[(uint32_t)(n0 + bn0) * (IN_F / 16) + (kt + 1) * 4 + bq0];
            wv[1] = w4g[(uint32_t)(n0 + bn1) * (IN_F / 16) + (kt + 1) * 4 + bq1];
        }

        CP_WAIT0();
        __syncthreads();   // tile kt fully resident (A cp.async + B STS)

        // issue next A tile via cp.async
        if (more) {
            const uint32_t ab = sb + OFF_TILE + (uint32_t)((kt + 1) & 1) * TILE_STRIDE;
            const int kk = (kt + 1) * BK + cj * 8;
            #pragma unroll
            for (int i = 0; i < 4; i++) {
                int m = cm + i * 32;
                uint32_t dst = ab + SWZ((uint32_t)m * 128 + (uint32_t)cj * 16);
                CP16(dst, gx + (size_t)(m0 + m) * IN_F + kk);
            }
        }
        CP_COMMIT();

        // ---- MMA on current buffer, decode interleaved per ks step ----
        {
            const uint32_t base = sb + OFF_TILE + (uint32_t)(kt & 1) * TILE_STRIDE;
            const uint32_t ahb = base + a_row;
            const uint32_t bbb = base + 16384 + b_row;
            const uint32_t bnx = sb + OFF_TILE + (uint32_t)((kt + 1) & 1) * TILE_STRIDE + 16384;
            #pragma unroll
            for (int ks = 0; ks < 4; ks++) {
                const uint32_t koffa = ((uint32_t)(ks * 32) + a_kx) ^ axor;
                const uint32_t koffb = ((uint32_t)(ks * 32) + b_kx) ^ bxor;
                uint32_t bf[8];
                LDSM4(bf,     bbb + koffb);          // n atoms 0,1
                LDSM4(bf + 4, bbb + 2048 + koffb);   // n atoms 2,3
                #pragma unroll
                for (int ma = 0; ma < 4; ma++) {
                    uint32_t af[4];
                    LDSM4(af, ahb + (uint32_t)ma * 2048 + koffa);
                    MMA16816(acc[ma][0], af, bf[0], bf[1]);
                    MMA16816(acc[ma][1], af, bf[2], bf[3]);
                    MMA16816(acc[ma][2], af, bf[4], bf[5]);
                    MMA16816(acc[ma][3], af, bf[6], bf[7]);

                    // interleaved decode: one quarter of next B tile per ks,
                    // issued mid-MMA so ALU/STS hide in the tensor-op shadow
                    if (ma == 1 && more) {
                        const int i  = ks >> 1;
                        const int hf = ks & 1;
                        int wa = hf ? wv[i].z : wv[i].x;
                        int wb = hf ? wv[i].w : wv[i].y;
                        uint2 da = dec_word(wa), db = dec_word(wb);
                        uint32_t o0 = (i ? bo1 : bo0) + (uint32_t)hf * 16;
                        asm volatile("st.shared.v4.b32 [%0], {%1,%2,%3,%4};"
                            :: "r"(bnx + SWZ(o0)),
                               "r"(da.x), "r"(da.y), "r"(db.x), "r"(db.y));
                    }
                }
            }
        }
    }

    // ---------------- epilogue ----------------
    const float* alpS = reinterpret_cast<const float*>(smem + OFF_ALPHA);
    const float* biaS = reinterpret_cast<const float*>(smem + OFF_BIAS);
    const int r  = L >> 2;
    const int c2 = (L & 3) * 2;

    #pragma unroll
    for (int ma = 0; ma < 4; ma++) {
        #pragma unroll
        for (int na = 0; na < 4; na++) {
            int cl = wn + na * 8 + c2;
            float A0 = alpS[cl], A1 = alpS[cl + 1];
            float B0 = biaS[cl], B1 = biaS[cl + 1];
            int gm = m0 + wm + ma * 16 + r;
            float* p = out + (uint32_t)gm * OUT_F + n0 + cl;
            float2 v0 = make_float2(fmaf(acc[ma][na][0], A0, B0),
                                    fmaf(acc[ma][na][1], A1, B1));
            *reinterpret_cast<float2*>(p) = v0;
            float2 v1 = make_float2(fmaf(acc[ma][na][2], A0, B0),
                                    fmaf(acc[ma][na][3], A1, B1));
            *reinterpret_cast<float2*>(p + 8 * OUT_F) = v1;
        }
    }
}

extern "C" void kernel_launch(void* const* d_in, const int* in_sizes, int n_in,
                              void* d_out, int out_size) {
    const float* x     = (const float*)d_in[0];
    const int*   wp    = (const int*)d_in[1];
    const float* alpha = (const float*)d_in[2];
    const float* bias  = (const float*)d_in[3];
    float*       out   = (float*)d_out;

    static bool configured = false;
    if (!configured) {
        cudaFuncSetAttribute(ternary_gemm_fp16,
                             cudaFuncAttributeMaxDynamicSharedMemorySize, SMEM_BYTES);
        configured = true;
    }

    // pre-kernel: x fp32 -> fp16 (4 MB)
    conv_x_fp16<<<TOKENS * IN_F / 4 / 256, 256>>>(
        reinterpret_cast<const float4*>(x));

    dim3 grid(OUT_F / BN, TOKENS / BM);   // (64, 4) = 256 CTAs
    ternary_gemm_fp16<<<grid, NTHREADS, SMEM_BYTES>>>(wp, alpha, bias, out);
}